// round 11
// baseline (speedup 1.0000x reference)
#include <cuda_runtime.h>
#include <math.h>

// Problem shape (fixed by the dataset): [B=32, C=1, H=512, W=512] fp32.
#define BATCH 32
#define HH 512
#define WW 512
#define W4 (WW / 4)       // 128 float4 per row
#define KER 31
#define PAD 15
#define NPIX (HH * WW)
#define ROWS 16           // output rows per block
#define TILES (HH / ROWS) // 32
#define NBLOCKS (TILES * BATCH)  // 1024

// Per-(batch,tile) partials: x=sum(weit), y=sum(weit*bce), z=inter, w=union
__device__ float4 g_part[BATCH][TILES];
__device__ int g_count = 0;   // last-block detector; self-resets each launch

__inline__ __device__ float warp_reduce(float v) {
    #pragma unroll
    for (int o = 16; o > 0; o >>= 1) v += __shfl_down_sync(0xffffffffu, v, o);
    return v;
}

// ln(1+u) on (0,1], Abramowitz&Stegun 4.1.44, |err| < 1e-5.
// Validated in R9: end-to-end rel_err unchanged (8.1e-8). 5 FMA + 1 MUL,
// replaces the MUFU lg2 path of __logf and shortens the exp->log chain.
__inline__ __device__ float log1p_poly(float u) {
    float r = 0.03215845f;
    r = fmaf(r, u, -0.13606275f);
    r = fmaf(r, u,  0.28947478f);
    r = fmaf(r, u, -0.49190896f);
    r = fmaf(r, u,  0.99949556f);
    return r * u;
}

// Padded per-row buffers: float4 index 4+tid holds thread tid's vsum (cols
// 4t..4t+3); indices 0..3 and 132..135 are zero pads. G[i] = sum4(P[i]).
__global__ void __launch_bounds__(128, 8)
structure_loss_kernel(const float* __restrict__ x,
                      const float* __restrict__ t,
                      float* __restrict__ out) {
    __shared__ float4 Pb[2][136];
    __shared__ float  Gb[2][136];
    __shared__ float red4[4][4];
    __shared__ float sl[BATCH];
    __shared__ int s_last;

    const int tid  = threadIdx.x;   // 0..127, owns cols 4*tid..4*tid+3
    const int tile = blockIdx.x;    // 0..31
    const int b    = blockIdx.y;    // 0..31
    const int h0   = tile * ROWS;

    // zero the pads of both buffers (read-only thereafter)
    if (tid < 4) {
        const float4 z4 = make_float4(0.f, 0.f, 0.f, 0.f);
        Pb[0][tid] = z4;       Pb[1][tid] = z4;
        Pb[0][132 + tid] = z4; Pb[1][132 + tid] = z4;
        Gb[0][tid] = 0.f;       Gb[1][tid] = 0.f;
        Gb[0][132 + tid] = 0.f; Gb[1][132 + tid] = 0.f;
    }

    const float4* tc = (const float4*)(t + (size_t)b * NPIX) + tid;

    // ---- initial vertical window for row h0: rows [h0-15, h0+15] clipped ----
    float4 s = make_float4(0.f, 0.f, 0.f, 0.f);
    {
        const int lo = (h0 - PAD < 0) ? 0 : h0 - PAD;
        const int hi = (h0 + PAD > HH - 1) ? HH - 1 : h0 + PAD;
        #pragma unroll 8
        for (int r = lo; r <= hi; ++r) {
            float4 q = tc[(size_t)r * W4];
            s.x += q.x; s.y += q.y; s.z += q.z; s.w += q.w;
        }
    }

    float a0 = 0.f, a1 = 0.f, a2 = 0.f, a3 = 0.f;
    const float inv = 1.0f / (float)(KER * KER);

    #pragma unroll 2
    for (int j = 0; j < ROWS; ++j) {
        if (j > 0) {  // slide the vertical window down one row
            const int add = h0 + j + PAD;
            const int sub = h0 + j - PAD - 1;
            if (add < HH) {
                float4 q = tc[(size_t)add * W4];
                s.x += q.x; s.y += q.y; s.z += q.z; s.w += q.w;
            }
            if (sub >= 0) {
                float4 q = tc[(size_t)sub * W4];
                s.x -= q.x; s.y -= q.y; s.z -= q.z; s.w -= q.w;
            }
        }

        float4* P = Pb[j & 1];
        float*  G = Gb[j & 1];
        P[4 + tid] = s;
        G[4 + tid] = (s.x + s.y) + (s.z + s.w);
        __syncthreads();

        // horizontal 31-tap via group sums + neighbor edges
        const float4 sm = P[tid];      // cols 4t-16 .. 4t-13
        const float4 sp = P[tid + 8];  // cols 4t+16 .. 4t+19
        float S0 = G[tid] - sm.x;
        #pragma unroll
        for (int i = 1; i < 8; ++i) S0 += G[tid + i];
        const float S1 = S0 - sm.y + sp.x;
        const float S2 = S1 - sm.z + sp.y;
        const float S3 = S2 - sm.w + sp.z;
        const float S[4] = {S0, S1, S2, S3};

        const size_t rowoff = ((size_t)b * HH + h0 + j) * (size_t)WW + 4 * tid;
        const float4 t4 = *(const float4*)(t + rowoff);
        const float4 x4 = *(const float4*)(x + rowoff);
        const float tt_[4] = {t4.x, t4.y, t4.z, t4.w};
        const float xx_[4] = {x4.x, x4.y, x4.z, x4.w};

        #pragma unroll
        for (int k = 0; k < 4; ++k) {
            const float tt = tt_[k];
            const float xx = xx_[k];
            const float weit = 1.0f + 5.0f * fabsf(S[k] * inv - tt);
            const float e    = __expf(-fabsf(xx));                 // e^{-|x|}
            const float bce  = fmaxf(xx, 0.0f) - xx * tt + log1p_poly(e);
            const float p    = __fdividef((xx >= 0.0f ? 1.0f : e), 1.0f + e);
            a0 += weit;
            a1 += weit * bce;
            a2 += p * tt * weit;
            a3 += (p + tt) * weit;
        }
    }

    // ---- block reduce -> one float4 per block ----
    a0 = warp_reduce(a0);
    a1 = warp_reduce(a1);
    a2 = warp_reduce(a2);
    a3 = warp_reduce(a3);
    const int warp = tid >> 5;
    const int lane = tid & 31;
    if (lane == 0) {
        red4[warp][0] = a0; red4[warp][1] = a1;
        red4[warp][2] = a2; red4[warp][3] = a3;
    }
    __syncthreads();

    if (tid == 0) {
        float4 r;
        r.x = (red4[0][0] + red4[1][0]) + (red4[2][0] + red4[3][0]);
        r.y = (red4[0][1] + red4[1][1]) + (red4[2][1] + red4[3][1]);
        r.z = (red4[0][2] + red4[1][2]) + (red4[2][2] + red4[3][2]);
        r.w = (red4[0][3] + red4[1][3]) + (red4[2][3] + red4[3][3]);
        g_part[b][tile] = r;
        __threadfence();
        int prev = atomicAdd(&g_count, 1);
        s_last = (prev == NBLOCKS - 1) ? 1 : 0;
        if (s_last) atomicExch(&g_count, 0);   // reset for next graph replay
    }
    __syncthreads();
    if (!s_last) return;

    // ---- last block: final reduction (fixed order => deterministic) ----
    __threadfence();  // acquire: see all g_part writes
    {
        // thread i: batch bb = i>>2, quarter p = i&3 -> tiles p*8 .. p*8+7
        const int bb = tid >> 2;
        const int p  = tid & 3;
        float c0 = 0.f, c1 = 0.f, c2 = 0.f, c3 = 0.f;
        #pragma unroll
        for (int k = 0; k < TILES / 4; ++k) {
            float4 q = g_part[bb][p * (TILES / 4) + k];
            c0 += q.x; c1 += q.y; c2 += q.z; c3 += q.w;
        }
        #pragma unroll
        for (int o = 1; o <= 2; o <<= 1) {
            c0 += __shfl_xor_sync(0xffffffffu, c0, o);
            c1 += __shfl_xor_sync(0xffffffffu, c1, o);
            c2 += __shfl_xor_sync(0xffffffffu, c2, o);
            c3 += __shfl_xor_sync(0xffffffffu, c3, o);
        }
        if (p == 0) {
            const float wbce = c1 / c0;
            const float wiou = 1.0f - (c2 + 1.0f) / ((c3 - c2) + 1.0f);
            sl[bb] = wbce + wiou;
        }
    }
    __syncthreads();
    if (tid < 32) {
        float l = sl[tid];
        l = warp_reduce(l);
        if (tid == 0) out[0] = l * (1.0f / (float)BATCH);
    }
}

// ---------------------------------------------------------------------------
extern "C" void kernel_launch(void* const* d_in, const int* in_sizes, int n_in,
                              void* d_out, int out_size) {
    const float* x = (const float*)d_in[0];  // input (logits)
    const float* t = (const float*)d_in[1];  // target
    float* out = (float*)d_out;

    dim3 grid(TILES, BATCH);
    structure_loss_kernel<<<grid, 128>>>(x, t, out);
}

// round 12
// speedup vs baseline: 1.6204x; 1.6204x over previous
#include <cuda_runtime.h>
#include <math.h>

// Problem shape (fixed by the dataset): [B=32, C=1, H=512, W=512] fp32.
#define BATCH 32
#define HH 512
#define WW 512
#define W4 (WW / 4)       // 128 float4 per row
#define KER 31
#define PAD 15
#define NPIX (HH * WW)
#define ROWS 16           // output rows per block
#define TILES (HH / ROWS) // 32
#define NBLOCKS (TILES * BATCH)  // 1024

// Per-(batch,tile) partials: x=sum(weit), y=sum(weit*bce), z=inter, w=union
__device__ float4 g_part[BATCH][TILES];
__device__ int g_count = 0;   // last-block detector; self-resets each launch

__inline__ __device__ float warp_reduce(float v) {
    #pragma unroll
    for (int o = 16; o > 0; o >>= 1) v += __shfl_down_sync(0xffffffffu, v, o);
    return v;
}

// Padded per-row buffers: float4 index 4+tid holds thread tid's vsum (cols
// 4t..4t+3); indices 0..3 and 132..135 are zero pads. G[i] = sum4(P[i]).
__global__ void __launch_bounds__(128, 7)
structure_loss_kernel(const float* __restrict__ x,
                      const float* __restrict__ t,
                      float* __restrict__ out) {
    __shared__ float4 Pb[2][136];
    __shared__ float  Gb[2][136];
    __shared__ float red4[4][4];
    __shared__ float sl[BATCH];
    __shared__ int s_last;

    const int tid  = threadIdx.x;   // 0..127, owns cols 4*tid..4*tid+3
    const int tile = blockIdx.x;    // 0..31
    const int b    = blockIdx.y;    // 0..31
    const int h0   = tile * ROWS;

    // zero the pads of both buffers (read-only thereafter)
    if (tid < 4) {
        const float4 z4 = make_float4(0.f, 0.f, 0.f, 0.f);
        Pb[0][tid] = z4;       Pb[1][tid] = z4;
        Pb[0][132 + tid] = z4; Pb[1][132 + tid] = z4;
        Gb[0][tid] = 0.f;       Gb[1][tid] = 0.f;
        Gb[0][132 + tid] = 0.f; Gb[1][132 + tid] = 0.f;
    }

    // 32-bit indexing: all offsets < 2^23 float4s
    const int base = b * (NPIX / 4);  // float4 units
    const float4* tc = (const float4*)t + base + tid;
    const float4* xc = (const float4*)x + base + tid;

    // ---- initial vertical window for row h0: rows [h0-15, h0+15] clipped ----
    float4 s = make_float4(0.f, 0.f, 0.f, 0.f);
    {
        const int lo = (h0 - PAD < 0) ? 0 : h0 - PAD;
        const int hi = (h0 + PAD > HH - 1) ? HH - 1 : h0 + PAD;
        #pragma unroll 8
        for (int r = lo; r <= hi; ++r) {
            float4 q = tc[r * W4];
            s.x += q.x; s.y += q.y; s.z += q.z; s.w += q.w;
        }
    }

    // prefetch t/x for row h0 (consumed after the first barrier)
    int crow = h0 * W4;
    float4 t4 = tc[crow];
    float4 x4 = xc[crow];

    float a0 = 0.f, a1 = 0.f, a2 = 0.f, a3 = 0.f;
    const float inv = 1.0f / (float)(KER * KER);

    #pragma unroll 2
    for (int j = 0; j < ROWS; ++j) {
        float4* P = Pb[j & 1];
        float*  G = Gb[j & 1];
        P[4 + tid] = s;
        G[4 + tid] = (s.x + s.y) + (s.z + s.w);
        __syncthreads();

        // ---- early-issue ALL next-row global loads (in flight during compute)
        const bool more = (j < ROWS - 1);
        const bool ha = (h0 + j + 1 + PAD) < HH;   // add row for slide j->j+1
        const bool hs = (h0 + j - PAD) >= 0;       // sub row for slide j->j+1
        float4 qa, qs, t4n, x4n;
        if (more) {
            if (ha) qa = tc[(h0 + j + 1 + PAD) * W4];
            if (hs) qs = tc[(h0 + j - PAD) * W4];
            t4n = tc[crow + W4];
            x4n = xc[crow + W4];
        }

        // ---- horizontal 31-tap via group sums + neighbor edges ----
        const float4 sm = P[tid];      // cols 4t-16 .. 4t-13
        const float4 sp = P[tid + 8];  // cols 4t+16 .. 4t+19
        float S0 = G[tid] - sm.x;
        #pragma unroll
        for (int i = 1; i < 8; ++i) S0 += G[tid + i];
        const float S1 = S0 - sm.y + sp.x;
        const float S2 = S1 - sm.z + sp.y;
        const float S3 = S2 - sm.w + sp.z;
        const float S[4]   = {S0, S1, S2, S3};
        const float tt_[4] = {t4.x, t4.y, t4.z, t4.w};
        const float xx_[4] = {x4.x, x4.y, x4.z, x4.w};

        #pragma unroll
        for (int k = 0; k < 4; ++k) {
            const float tt = tt_[k];
            const float xx = xx_[k];
            const float d    = fmaf(S[k], inv, -tt);
            const float weit = fmaf(fabsf(d), 5.0f, 1.0f);
            const float e    = __expf(-fabsf(xx));              // e^{-|x|}
            const float ope  = 1.0f + e;
            const float bce  = fmaxf(xx, 0.0f) - xx * tt + __logf(ope);
            const float p    = __fdividef((xx >= 0.0f ? 1.0f : e), ope);
            a0 += weit;
            a1 = fmaf(weit, bce, a1);
            a2 = fmaf(p * tt, weit, a2);
            a3 = fmaf(p + tt, weit, a3);
        }

        // ---- consume the prefetched loads: slide window, roll t/x ----
        if (more) {
            if (ha) { s.x += qa.x; s.y += qa.y; s.z += qa.z; s.w += qa.w; }
            if (hs) { s.x -= qs.x; s.y -= qs.y; s.z -= qs.z; s.w -= qs.w; }
            t4 = t4n; x4 = x4n;
            crow += W4;
        }
    }

    // ---- block reduce -> one float4 per block ----
    a0 = warp_reduce(a0);
    a1 = warp_reduce(a1);
    a2 = warp_reduce(a2);
    a3 = warp_reduce(a3);
    const int warp = tid >> 5;
    const int lane = tid & 31;
    if (lane == 0) {
        red4[warp][0] = a0; red4[warp][1] = a1;
        red4[warp][2] = a2; red4[warp][3] = a3;
    }
    __syncthreads();

    if (tid == 0) {
        float4 r;
        r.x = (red4[0][0] + red4[1][0]) + (red4[2][0] + red4[3][0]);
        r.y = (red4[0][1] + red4[1][1]) + (red4[2][1] + red4[3][1]);
        r.z = (red4[0][2] + red4[1][2]) + (red4[2][2] + red4[3][2]);
        r.w = (red4[0][3] + red4[1][3]) + (red4[2][3] + red4[3][3]);
        g_part[b][tile] = r;
        __threadfence();
        int prev = atomicAdd(&g_count, 1);
        s_last = (prev == NBLOCKS - 1) ? 1 : 0;
        if (s_last) atomicExch(&g_count, 0);   // reset for next graph replay
    }
    __syncthreads();
    if (!s_last) return;

    // ---- last block: final reduction (fixed order => deterministic) ----
    __threadfence();  // acquire: see all g_part writes
    {
        // thread i: batch bb = i>>2, quarter p = i&3 -> tiles p*8 .. p*8+7
        const int bb = tid >> 2;
        const int p  = tid & 3;
        float c0 = 0.f, c1 = 0.f, c2 = 0.f, c3 = 0.f;
        #pragma unroll
        for (int k = 0; k < TILES / 4; ++k) {
            float4 q = g_part[bb][p * (TILES / 4) + k];
            c0 += q.x; c1 += q.y; c2 += q.z; c3 += q.w;
        }
        #pragma unroll
        for (int o = 1; o <= 2; o <<= 1) {
            c0 += __shfl_xor_sync(0xffffffffu, c0, o);
            c1 += __shfl_xor_sync(0xffffffffu, c1, o);
            c2 += __shfl_xor_sync(0xffffffffu, c2, o);
            c3 += __shfl_xor_sync(0xffffffffu, c3, o);
        }
        if (p == 0) {
            const float wbce = c1 / c0;
            const float wiou = 1.0f - (c2 + 1.0f) / ((c3 - c2) + 1.0f);
            sl[bb] = wbce + wiou;
        }
    }
    __syncthreads();
    if (tid < 32) {
        float l = sl[tid];
        l = warp_reduce(l);
        if (tid == 0) out[0] = l * (1.0f / (float)BATCH);
    }
}

// ---------------------------------------------------------------------------
extern "C" void kernel_launch(void* const* d_in, const int* in_sizes, int n_in,
                              void* d_out, int out_size) {
    const float* x = (const float*)d_in[0];  // input (logits)
    const float* t = (const float*)d_in[1];  // target
    float* out = (float*)d_out;

    dim3 grid(TILES, BATCH);
    structure_loss_kernel<<<grid, 128>>>(x, t, out);
}